// round 16
// baseline (speedup 1.0000x reference)
#include <cuda_runtime.h>
#include <math.h>
#include <stdint.h>

#define BW 64
#define BO 64
#define TW 32
#define TO 36
#define DD 512
#define SCALE 0.044194173824159216f  // 1/sqrt(512)
#define NTHR 576
#define NCTA 148
#define NTILE (BW * BO)

#define WHS 260     // w hi/lo word stride (words of bf16x2), 260%32=4
#define UHS 260     // u hi/lo word stride
#define ATS 28      // att word stride
#define OROWS 24    // global o-pair rows (18 data + 6 zero pad)
#define OSTRG 520   // global o row stride (words), data at col 1+d

// smem layout (4-byte word offsets)
#define OFF_WH   0          // 32*260 = 8320
#define OFF_WL   8320       // 8320
#define OFF_UH   16640      // 40*260 = 10400 (rows 36-39 zero)
#define OFF_UL   27040      // 10400
#define OFF_P2   37440      // 8*1280 = 10240
#define OFF_ATTC 47680      // 1168
#define OFF_ATH  48848      // 32*28 = 896
#define OFF_ATL  49744      // 896
#define OFF_LGP  50640      // 512
#define OFF_LGP2 51152      // 224
#define OFF_WP   51376      // 8 floats warp_part
#define OFF_FIN  51384      // int[4] finish list
#define OFF_NF   51388      // int
#define OFF_FLAG 51389      // int
#define SMEM_FLOATS 51392   // 205568 bytes

__device__ float g_logits[BW * TW * BO];   // [wb][t][ob]
__device__ float g_partial[BW];
__device__ int   cnt_wb[BW];
__device__ int   cnt_done;

// precomputed bf16 splits (hi + residual), packed bf16x2
__device__ uint32_t d_wh[BW * TW * 256];           // [wb][t][dw]
__device__ uint32_t d_wl[BW * TW * 256];
__device__ uint32_t d_uh[BO * TO * 256];           // [ob][o][dw]
__device__ uint32_t d_ul[BO * TO * 256];
__device__ uint32_t d_oh[BO * OROWS * OSTRG];      // [ob][r][1+d], pads zero
__device__ uint32_t d_ol[BO * OROWS * OSTRG];

__device__ __forceinline__ uint32_t packsplit(float x, float y, uint32_t &lo) {
    uint32_t h;
    asm("cvt.rn.satfinite.bf16x2.f32 %0, %1, %2;" : "=r"(h) : "f"(y), "f"(x));
    float hx = __uint_as_float(h << 16);
    float hy = __uint_as_float(h & 0xffff0000u);
    float rx = x - hx, ry = y - hy;
    asm("cvt.rn.satfinite.bf16x2.f32 %0, %1, %2;" : "=r"(lo) : "f"(ry), "f"(rx));
    return h;
}
__device__ __forceinline__ float bfhalf(uint32_t w, int odd) {
    return __uint_as_float(odd ? (w & 0xffff0000u) : (w << 16));
}
__device__ __forceinline__ void mma_bf16(float* c, const uint32_t* a,
                                         uint32_t b0, uint32_t b1) {
    asm("mma.sync.aligned.m16n8k16.row.col.f32.bf16.bf16.f32 "
        "{%0,%1,%2,%3}, {%4,%5,%6,%7}, {%8,%9}, {%0,%1,%2,%3};"
        : "+f"(c[0]), "+f"(c[1]), "+f"(c[2]), "+f"(c[3])
        : "r"(a[0]), "r"(a[1]), "r"(a[2]), "r"(a[3]), "r"(b0), "r"(b1));
}

// ---------------- pre-kernel: bf16-split all inputs + zero pads/counters ----
#define NW (BW * TW * 128)
#define NU (BO * TO * 128)
#define NO (BO * 18 * 128)
#define NZ1 (BO * 6 * OSTRG)    // o pad rows 18-23
#define NZ2 (BO * 18 * 8)       // o rows 0-17: word 0 + words 513-519

__global__ void cap_prep(const float* __restrict__ g_o,
                         const float* __restrict__ g_u,
                         const float* __restrict__ g_w)
{
    int idx = blockIdx.x * blockDim.x + threadIdx.x;
    if (idx < BW) cnt_wb[idx] = 0;
    if (idx == BW) cnt_done = 0;

    if (idx < NW) {
        float4 v = reinterpret_cast<const float4*>(g_w)[idx];
        uint32_t l0, l1;
        uint32_t h0 = packsplit(v.x, v.y, l0);
        uint32_t h1 = packsplit(v.z, v.w, l1);
        reinterpret_cast<uint2*>(d_wh)[idx] = make_uint2(h0, h1);
        reinterpret_cast<uint2*>(d_wl)[idx] = make_uint2(l0, l1);
    } else if (idx < NW + NU) {
        int j = idx - NW;
        float4 v = reinterpret_cast<const float4*>(g_u)[j];
        uint32_t l0, l1;
        uint32_t h0 = packsplit(v.x, v.y, l0);
        uint32_t h1 = packsplit(v.z, v.w, l1);
        reinterpret_cast<uint2*>(d_uh)[j] = make_uint2(h0, h1);
        reinterpret_cast<uint2*>(d_ul)[j] = make_uint2(l0, l1);
    } else if (idx < NW + NU + NO) {
        int j = idx - NW - NU;
        int bop = j >> 7, c = j & 127;        // bop = ob*18+op
        int b = bop / 18, op = bop % 18;
        const float* rA = g_o + ((size_t)(b * TO + 2 * op)) * 512 + 4 * c;
        float4 A = *reinterpret_cast<const float4*>(rA);
        float4 B = *reinterpret_cast<const float4*>(rA + 512);
        uint32_t h[4], l[4];
        h[0] = packsplit(A.x, B.x, l[0]);
        h[1] = packsplit(A.y, B.y, l[1]);
        h[2] = packsplit(A.z, B.z, l[2]);
        h[3] = packsplit(A.w, B.w, l[3]);
        uint32_t* dh = d_oh + b * (OROWS * OSTRG) + op * OSTRG + 1 + 4 * c;
        uint32_t* dl = d_ol + b * (OROWS * OSTRG) + op * OSTRG + 1 + 4 * c;
        dh[0] = h[0]; dh[1] = h[1]; dh[2] = h[2]; dh[3] = h[3];
        dl[0] = l[0]; dl[1] = l[1]; dl[2] = l[2]; dl[3] = l[3];
    } else if (idx < NW + NU + NO + NZ1) {
        int j = idx - (NW + NU + NO);
        int b = j / (6 * OSTRG), rem = j % (6 * OSTRG);
        int off = b * (OROWS * OSTRG) + 18 * OSTRG + rem;
        d_oh[off] = 0u; d_ol[off] = 0u;
    } else if (idx < NW + NU + NO + NZ1 + NZ2) {
        int j = idx - (NW + NU + NO + NZ1);
        int b = j / 144, rem = j % 144;
        int r = rem >> 3, wsel = rem & 7;
        int col = wsel ? (512 + wsel) : 0;
        int off = b * (OROWS * OSTRG) + r * OSTRG + col;
        d_oh[off] = 0u; d_ol[off] = 0u;
    }
}

extern __shared__ float smem[];

__global__ __launch_bounds__(NTHR, 1)
void cap_main(const int* __restrict__ g_mask,
              float* __restrict__ out,       // loss scalar (= d_out)
              float* __restrict__ out_att,   // = d_out + 1
              float* __restrict__ out_avo)   // = d_out + 1 + 64*64*32*36
{
    const int tid = threadIdx.x;

    uint32_t* wh  = (uint32_t*)(smem + OFF_WH);
    uint32_t* wl  = (uint32_t*)(smem + OFF_WL);
    uint32_t* uh  = (uint32_t*)(smem + OFF_UH);
    uint32_t* ul  = (uint32_t*)(smem + OFF_UL);
    float*    p2     = smem + OFF_P2;
    float*    att_cs = smem + OFF_ATTC;
    uint32_t* ath    = (uint32_t*)(smem + OFF_ATH);
    uint32_t* atl    = (uint32_t*)(smem + OFF_ATL);
    float*    lgp    = smem + OFF_LGP;
    float*    lgp2   = smem + OFF_LGP2;
    float*    warp_part = smem + OFF_WP;
    int*      fin    = (int*)(smem + OFF_FIN);
    int*      nfp    = (int*)(smem + OFF_NF);
    int*      flagp  = (int*)(smem + OFF_FLAG);

    const int wrp  = tid >> 5;
    const int lane = tid & 31;
    const int g    = lane >> 2;      // mma groupID
    const int tg   = lane & 3;       // mma threadID in group

    // persistent chunked schedule: CTA owns tiles [t0, t1)
    const int per = (NTILE + NCTA - 1) / NCTA;           // 28
    const int t0c = blockIdx.x * per;
    const int t1c = (t0c + per < NTILE) ? (t0c + per) : NTILE;

    // hoisted pads (regions untouched by loop bodies)
    if (tid < 192) {                 // att k-pad words 18-23
        int r = tid / 6, j = tid % 6;
        ath[r * ATS + 18 + j] = 0u;
        atl[r * ATS + 18 + j] = 0u;
    }
    for (int idx = tid; idx < 4 * UHS; idx += NTHR) {   // u n-pad rows 36-39
        uh[36 * UHS + idx] = 0u;
        ul[36 * UHS + idx] = 0u;
    }
    if (tid == 0) *nfp = 0;

    int prev_wb = -1;
    for (int tile = t0c; tile < t1c; tile++) {
        const int wb  = tile >> 6;
        const int ob  = tile & 63;
        const int blk = tile;
        const uint32_t* goh = d_oh + ob * (OROWS * OSTRG);
        const uint32_t* gol = d_ol + ob * (OROWS * OSTRG);

        // ---------- phase 1: copy pre-split w (if wb changed) and u ---------
        if (wb != prev_wb) {
            const uint4* gwh = reinterpret_cast<const uint4*>(d_wh + wb * (TW * 256));
            const uint4* gwl = reinterpret_cast<const uint4*>(d_wl + wb * (TW * 256));
            for (int idx = tid; idx < TW * 64; idx += NTHR) {
                int t = idx >> 6, q = idx & 63;
                *reinterpret_cast<uint4*>(&wh[t * WHS + 4 * q]) = gwh[idx];
                *reinterpret_cast<uint4*>(&wl[t * WHS + 4 * q]) = gwl[idx];
            }
        }
        prev_wb = wb;
        {
            const uint4* guh = reinterpret_cast<const uint4*>(d_uh + ob * (TO * 256));
            const uint4* gul = reinterpret_cast<const uint4*>(d_ul + ob * (TO * 256));
            for (int idx = tid; idx < TO * 64; idx += NTHR) {
                int o = idx >> 6, q = idx & 63;
                *reinterpret_cast<uint4*>(&uh[o * UHS + 4 * q]) = guh[idx];
                *reinterpret_cast<uint4*>(&ul[o * UHS + 4 * q]) = gul[idx];
            }
        }
        __syncthreads();

        // ---------- phase 2: scores via bf16 mma (3-term, k16) --------------
        if (wrp < 16) {
            const int mt = wrp & 1;
            const int ks = wrp >> 1;

            float c[5][4];
            #pragma unroll
            for (int nt = 0; nt < 5; nt++)
                #pragma unroll
                for (int q = 0; q < 4; q++) c[nt][q] = 0.f;

            const uint32_t* whr0 = wh + (16 * mt + g) * WHS;
            const uint32_t* whr1 = whr0 + 8 * WHS;
            const uint32_t* wlr0 = wl + (16 * mt + g) * WHS;
            const uint32_t* wlr1 = wlr0 + 8 * WHS;

            #pragma unroll
            for (int j = 0; j < 4; j++) {
                const int kw = ks * 32 + j * 8;
                uint32_t ah[4], al[4];
                ah[0] = whr0[kw + tg];     ah[1] = whr1[kw + tg];
                ah[2] = whr0[kw + tg + 4]; ah[3] = whr1[kw + tg + 4];
                al[0] = wlr0[kw + tg];     al[1] = wlr1[kw + tg];
                al[2] = wlr0[kw + tg + 4]; al[3] = wlr1[kw + tg + 4];
                #pragma unroll
                for (int nt = 0; nt < 5; nt++) {
                    const uint32_t* ur = uh + (8 * nt + g) * UHS + kw;
                    const uint32_t* lr = ul + (8 * nt + g) * UHS + kw;
                    uint32_t bh0 = ur[tg], bh1 = ur[tg + 4];
                    uint32_t bl0 = lr[tg], bl1 = lr[tg + 4];
                    mma_bf16(c[nt], ah, bh0, bh1);
                    mma_bf16(c[nt], ah, bl0, bl1);
                    mma_bf16(c[nt], al, bh0, bh1);
                }
            }
            float* pp = p2 + ks * 1280 + (16 * mt) * 40;
            #pragma unroll
            for (int nt = 0; nt < 5; nt++) {
                int col = 8 * nt + 2 * tg;
                *reinterpret_cast<float2*>(&pp[g * 40 + col])       = make_float2(c[nt][0], c[nt][1]);
                *reinterpret_cast<float2*>(&pp[(g + 8) * 40 + col]) = make_float2(c[nt][2], c[nt][3]);
            }
        }
        __syncthreads();

        // ---------- phase 3: warp-level softmax (no barriers) ---------------
        if (wrp < 16) {
            const int row = 2 * wrp + (lane >> 4);
            const int li  = lane & 15;
            const float* pr = p2 + row * 40;
            float s0 = 0.f, s1 = 0.f, s2 = 0.f, s3 = 0.f;
            #pragma unroll
            for (int ks = 0; ks < 8; ks++) {
                float2 v = *reinterpret_cast<const float2*>(&pr[ks * 1280 + 2 * li]);
                s0 += v.x; s1 += v.y;
                if (li < 2) {
                    float2 v2 = *reinterpret_cast<const float2*>(&pr[ks * 1280 + 32 + 2 * li]);
                    s2 += v2.x; s3 += v2.y;
                }
            }
            s0 *= SCALE; s1 *= SCALE; s2 *= SCALE; s3 *= SCALE;
            float m = fmaxf(s0, s1);
            if (li < 2) m = fmaxf(m, fmaxf(s2, s3));
            #pragma unroll
            for (int k = 1; k < 16; k <<= 1)
                m = fmaxf(m, __shfl_xor_sync(0xffffffffu, m, k));
            float e0 = expf(s0 - m), e1 = expf(s1 - m);
            float e2 = (li < 2) ? expf(s2 - m) : 0.f;
            float e3 = (li < 2) ? expf(s3 - m) : 0.f;
            float ss = e0 + e1 + e2 + e3;
            #pragma unroll
            for (int k = 1; k < 16; k <<= 1)
                ss += __shfl_xor_sync(0xffffffffu, ss, k);
            float inv = 1.f / ss;
            float a0 = e0 * inv, a1 = e1 * inv;

            att_cs[1 + row * TO + 2 * li]     = a0;
            att_cs[1 + row * TO + 2 * li + 1] = a1;
            uint32_t lo;
            uint32_t h = packsplit(a0, a1, lo);
            ath[row * ATS + li] = h;
            atl[row * ATS + li] = lo;
            if (li < 2) {
                float a2 = e2 * inv, a3 = e3 * inv;
                att_cs[1 + row * TO + 32 + 2 * li]     = a2;
                att_cs[1 + row * TO + 32 + 2 * li + 1] = a3;
                uint32_t lo2;
                uint32_t h2 = packsplit(a2, a3, lo2);
                ath[row * ATS + 16 + li] = h2;
                atl[row * ATS + 16 + li] = lo2;
            }
        }
        __syncthreads();

        // ---------- phase 4b (warps 0-15, o from GLOBAL) ∥ att+edges --------
        if (wrp < 16) {
            const int m0 = 7 + 32 * wrp;               // warp d base

            float c[2][4][4];
            #pragma unroll
            for (int mt2 = 0; mt2 < 2; mt2++)
                #pragma unroll
                for (int nt = 0; nt < 4; nt++)
                    #pragma unroll
                    for (int q = 0; q < 4; q++) c[mt2][nt][q] = 0.f;

            #pragma unroll
            for (int kk = 0; kk < 3; kk++) {
                uint32_t bh[4][2], bl[4][2];
                #pragma unroll
                for (int nt = 0; nt < 4; nt++) {
                    const int rb = (8 * nt + g) * ATS + 8 * kk + tg;
                    bh[nt][0] = ath[rb]; bh[nt][1] = ath[rb + 4];
                    bl[nt][0] = atl[rb]; bl[nt][1] = atl[rb + 4];
                }
                #pragma unroll
                for (int mt2 = 0; mt2 < 2; mt2++) {
                    const int mb = m0 + 16 * mt2;
                    const int base = (8 * kk + tg) * OSTRG + 1 + mb + g;
                    uint32_t ah[4], al[4];
                    ah[0] = goh[base];             ah[1] = goh[base + 8];
                    ah[2] = goh[base + 4 * OSTRG]; ah[3] = goh[base + 4 * OSTRG + 8];
                    al[0] = gol[base];             al[1] = gol[base + 8];
                    al[2] = gol[base + 4 * OSTRG]; al[3] = gol[base + 4 * OSTRG + 8];
                    #pragma unroll
                    for (int nt = 0; nt < 4; nt++) {
                        mma_bf16(c[mt2][nt], ah, bh[nt][0], bh[nt][1]);
                        mma_bf16(c[mt2][nt], ah, bl[nt][0], bl[nt][1]);
                        mma_bf16(c[mt2][nt], al, bh[nt][0], bh[nt][1]);
                    }
                }
            }

            float lgt[4][2];
            #pragma unroll
            for (int nt = 0; nt < 4; nt++) { lgt[nt][0] = 0.f; lgt[nt][1] = 0.f; }

            #pragma unroll
            for (int mt2 = 0; mt2 < 2; mt2++) {
                const int d0 = m0 + 16 * mt2 + g;      // d0 in [7, 511)
                const bool hi_ok = (d0 + 8 < 512);
                const int dw = d0 >> 1;
                const int odd = d0 & 1;
                #pragma unroll
                for (int nt = 0; nt < 4; nt++) {
                    const int t0 = 8 * nt + 2 * tg;
                    float* r0 = out_avo + ((size_t)blk * TW + t0) * DD;
                    float* r1 = r0 + DD;
                    r0[d0] = c[mt2][nt][0];
                    r1[d0] = c[mt2][nt][1];
                    float w00 = bfhalf(wh[t0 * WHS + dw], odd)       + bfhalf(wl[t0 * WHS + dw], odd);
                    float w10 = bfhalf(wh[(t0 + 1) * WHS + dw], odd) + bfhalf(wl[(t0 + 1) * WHS + dw], odd);
                    lgt[nt][0] += c[mt2][nt][0] * w00;
                    lgt[nt][1] += c[mt2][nt][1] * w10;
                    if (hi_ok) {
                        r0[d0 + 8] = c[mt2][nt][2];
                        r1[d0 + 8] = c[mt2][nt][3];
                        float w01 = bfhalf(wh[t0 * WHS + dw + 4], odd)       + bfhalf(wl[t0 * WHS + dw + 4], odd);
                        float w11 = bfhalf(wh[(t0 + 1) * WHS + dw + 4], odd) + bfhalf(wl[(t0 + 1) * WHS + dw + 4], odd);
                        lgt[nt][0] += c[mt2][nt][2] * w01;
                        lgt[nt][1] += c[mt2][nt][3] * w11;
                    }
                }
            }
            #pragma unroll
            for (int s = 4; s < 32; s <<= 1)
                #pragma unroll
                for (int nt = 0; nt < 4; nt++) {
                    lgt[nt][0] += __shfl_xor_sync(0xffffffffu, lgt[nt][0], s);
                    lgt[nt][1] += __shfl_xor_sync(0xffffffffu, lgt[nt][1], s);
                }
            if (g == 0) {
                #pragma unroll
                for (int nt = 0; nt < 4; nt++) {
                    lgp[(8 * nt + 2 * tg)     * 16 + wrp] = lgt[nt][0];
                    lgp[(8 * nt + 2 * tg + 1) * 16 + wrp] = lgt[nt][1];
                }
            }
        } else {
            // warps 16-17: att global store + edge columns d in [0,7)
            const int base = tid - 512;
            {
                const size_t ab = (size_t)blk * (TW * TO);
                for (int j = base; j < 287; j += 64) {
                    float4 v = *reinterpret_cast<const float4*>(&att_cs[4 + 4 * j]);
                    *reinterpret_cast<float4*>(&out_att[ab + 3 + 4 * j]) = v;
                }
                if (base == 63) {
                    out_att[ab + 0]    = att_cs[1];
                    out_att[ab + 1]    = att_cs[2];
                    out_att[ab + 2]    = att_cs[3];
                    out_att[ab + 1151] = att_cs[1152];
                }
            }
            #pragma unroll
            for (int rep = 0; rep < 4; rep++) {
                int task = base + 64 * rep;
                if (task < 224) {
                    int t = task / 7, e = task % 7;
                    float acc = 0.f;
                    #pragma unroll 4
                    for (int o = 0; o < TO; o++) {
                        int op = o >> 1, odd = o & 1;
                        float ov = bfhalf(goh[op * OSTRG + 1 + e], odd)
                                 + bfhalf(gol[op * OSTRG + 1 + e], odd);
                        acc += att_cs[1 + t * TO + o] * ov;
                    }
                    out_avo[((size_t)blk * TW + t) * DD + e] = acc;
                    int dw = e >> 1, odd = e & 1;
                    float wv = bfhalf(wh[t * WHS + dw], odd) + bfhalf(wl[t * WHS + dw], odd);
                    lgp2[task] = acc * wv;
                }
            }
        }
        __syncthreads();

        if (tid < 32) {
            float s = 0.f;
            #pragma unroll
            for (int k = 0; k < 16; k++) s += lgp[tid * 16 + k];
            #pragma unroll
            for (int e = 0; e < 7; e++)  s += lgp2[tid * 7 + e];
            g_logits[(wb * TW + tid) * BO + ob] = s;
            __threadfence();
            __syncwarp();
            if (tid == 0) {
                int old = atomicAdd(&cnt_wb[wb], 1);
                if (old == BO - 1) { fin[*nfp] = wb; *nfp = *nfp + 1; }
            }
        }
    }

    // ---------------- fused loss epilogue (threadfence-reduction) -----------
    __syncthreads();
    const int nfin = *nfp;
    for (int i = 0; i < nfin; i++) {
        const int fwb = fin[i];
        float nk = 0.f;
        if (tid < 256) {
            __threadfence();
            float keepl = 1.f - (float)g_mask[fwb * TW + lane];
            nk = keepl;
            #pragma unroll
            for (int s = 16; s; s >>= 1) nk += __shfl_xor_sync(0xffffffffu, nk, s);

            float acc = 0.f;
            #pragma unroll
            for (int k = 0; k < 4; k++) {
                int t = wrp + 8 * k;
                const float* row = g_logits + (fwb * TW + t) * BO;
                float v0 = row[lane], v1 = row[lane + 32];
                float m = fmaxf(v0, v1);
                #pragma unroll
                for (int s = 16; s; s >>= 1) m = fmaxf(m, __shfl_xor_sync(0xffffffffu, m, s));
                float e = expf(v0 - m) + expf(v1 - m);
                #pragma unroll
                for (int s = 16; s; s >>= 1) e += __shfl_xor_sync(0xffffffffu, e, s);
                float lse = m + logf(e);
                float dv = (fwb < 32) ? __shfl_sync(0xffffffffu, v0, fwb)
                                      : __shfl_sync(0xffffffffu, v1, fwb - 32);
                float kt = 1.f - (float)g_mask[fwb * TW + t];
                acc += kt * (dv - lse);
            }
            if (lane == 0) warp_part[wrp] = acc;
        }
        __syncthreads();
        if (tid == 0) {
            float s = 0.f;
            #pragma unroll
            for (int k = 0; k < 8; k++) s += warp_part[k];
            g_partial[fwb] = s / (nk + 1e-6f);
            __threadfence();
            int old = atomicAdd(&cnt_done, 1);
            *flagp = (old == BW - 1) ? 1 : 0;
        }
        __syncthreads();
        if (*flagp) {
            if (tid < 32) {
                __threadfence();
                float s = g_partial[tid] + g_partial[tid + 32];
                #pragma unroll
                for (int k = 16; k; k >>= 1) s += __shfl_xor_sync(0xffffffffu, s, k);
                if (tid == 0) out[0] = -s / 64.f;
            }
        }
        __syncthreads();
    }
}

extern "C" void kernel_launch(void* const* d_in, const int* in_sizes, int n_in,
                              void* d_out, int out_size)
{
    const float* g_o    = (const float*)d_in[0];
    const float* g_u    = (const float*)d_in[1];
    const float* g_w    = (const float*)d_in[2];
    const int*   g_mask = (const int*)d_in[3];

    float* out     = (float*)d_out;
    float* out_att = out + 1;
    float* out_avo = out_att + (size_t)BW * BO * TW * TO;

    const size_t SMEM_BYTES = (size_t)SMEM_FLOATS * sizeof(float);
    cudaFuncSetAttribute(cap_main, cudaFuncAttributeMaxDynamicSharedMemorySize,
                         (int)SMEM_BYTES);

    const int prep_total = NW + NU + NO + NZ1 + NZ2;
    cap_prep<<<(prep_total + 255) / 256, 256>>>(g_o, g_u, g_w);

    cap_main<<<NCTA, NTHR, SMEM_BYTES>>>(g_mask, out, out_att, out_avo);
}